// round 12
// baseline (speedup 1.0000x reference)
#include <cuda_runtime.h>
#include <cstdint>

// Window attention: B_=4096 windows, N=64 tok, C=256, H=8 heads, D=32. fp32 I/O.
//   r0: g_Xr = tf32-round(x)
//   t0: transpose+round w_qkv/w_proj -> g_W*T (tf32)
//   b0: g_BM[h][w] = bias+mask in MMA-fragment order
//   k1: 3-stage cp.async mma.sync tf32 GEMM, grid (n,m) for L2 reuse of A
//   k2: mma.sync tf32 attention; sP aliased onto sQ/sK -> 3 CTAs/SM
//   k3: same GEMM for proj
// (PTX target compute_103: tcgen05 unavailable; legacy mma.sync tf32 path.)

#define NWIN   4096
#define CDIM   256
#define NHEAD  8
#define SCALEF 0.17677669529663687f

__device__ float  g_QKV[(size_t)NWIN * 64 * 768];
__device__ float  g_O  [(size_t)NWIN * 64 * 256];
__device__ float  g_Xr [(size_t)NWIN * 64 * 256];
__device__ float  g_WqkvT [768 * 256];
__device__ float  g_WprojT[256 * 256];
__device__ float4 g_BM[8 * 64 * 1024];      // 8 MB: [h][w][wm][nt][gid][tig]

__device__ __forceinline__ float tf32r(float x) {
    float y; asm("cvt.rna.tf32.f32 %0, %1;" : "=f"(y) : "f"(x)); return y;
}
__device__ __forceinline__ uint32_t smem_u32(const void* p) {
    uint32_t a;
    asm("{ .reg .u64 t; cvta.to.shared.u64 t, %1; cvt.u32.u64 %0, t; }" : "=r"(a) : "l"(p));
    return a;
}
__device__ __forceinline__ void cp_async16(uint32_t dst, const void* src) {
    asm volatile("cp.async.cg.shared.global [%0], [%1], 16;" :: "r"(dst), "l"(src));
}
__device__ __forceinline__ void cp_commit() {
    asm volatile("cp.async.commit_group;" ::: "memory");
}
template<int N> __device__ __forceinline__ void cp_wait() {
    asm volatile("cp.async.wait_group %0;" :: "n"(N) : "memory");
}

// m16n8k8 tf32 mma: D += A(16x8,row) * B(8x8,col).
__device__ __forceinline__ void mma_tf32(float* d, const uint32_t* a, const uint32_t* b) {
    asm volatile(
        "mma.sync.aligned.m16n8k8.row.col.f32.tf32.tf32.f32 "
        "{%0,%1,%2,%3}, {%4,%5,%6,%7}, {%8,%9}, {%0,%1,%2,%3};"
        : "+f"(d[0]), "+f"(d[1]), "+f"(d[2]), "+f"(d[3])
        : "r"(a[0]), "r"(a[1]), "r"(a[2]), "r"(a[3]), "r"(b[0]), "r"(b[1]));
}

// ---------------------------------------------------------------------------
// Kernel r0: elementwise tf32 rounding (float4).
// ---------------------------------------------------------------------------
__global__ void round_tf32(const float4* __restrict__ in, float4* __restrict__ out)
{
    int i = blockIdx.x * blockDim.x + threadIdx.x;
    float4 v = in[i];
    v.x = tf32r(v.x); v.y = tf32r(v.y); v.z = tf32r(v.z); v.w = tf32r(v.w);
    out[i] = v;
}

// ---------------------------------------------------------------------------
// Kernel t0: transpose src[256, ncol] -> dst[ncol, 256], tf32-rounded.
// ---------------------------------------------------------------------------
__global__ void transpose_tf32(const float* __restrict__ src, float* __restrict__ dst, int ncol)
{
    __shared__ float tile[32][33];
    const int bx = blockIdx.x, by = blockIdx.y;
    const int tx = threadIdx.x, ty0 = threadIdx.y;
    #pragma unroll
    for (int j = 0; j < 32; j += 8)
        tile[ty0 + j][tx] = src[(size_t)(by * 32 + ty0 + j) * ncol + bx * 32 + tx];
    __syncthreads();
    #pragma unroll
    for (int j = 0; j < 32; j += 8)
        dst[(size_t)(bx * 32 + ty0 + j) * 256 + by * 32 + tx] = tf32r(tile[tx][ty0 + j]);
}

// ---------------------------------------------------------------------------
// Kernel b0: build bias+mask fragment table.
// ---------------------------------------------------------------------------
__global__ void bm_build(const float* __restrict__ mask, const float* __restrict__ bt,
                         float4* __restrict__ out)
{
    const int hw = blockIdx.x;             // 0..511
    const int h = hw >> 6, w = hw & 63;
    const int t = threadIdx.x;             // 256
    const int nt = t >> 5, gid = (t >> 2) & 7, tig = t & 3;
    const float* mrow = mask + (size_t)w * 4096;
    float4* op = out + (size_t)hw * 1024 + nt * 32 + gid * 4 + tig;
    const int c = nt * 8 + tig * 2;
    #pragma unroll
    for (int wm = 0; wm < 4; wm++) {
        const int r0 = wm * 16 + gid, r1 = r0 + 8;
        float4 v;
        v.x = bt[(r0 - c + 63) * 8 + h] + mrow[r0 * 64 + c];
        v.y = bt[(r0 - c + 62) * 8 + h] + mrow[r0 * 64 + c + 1];
        v.z = bt[(r1 - c + 63) * 8 + h] + mrow[r1 * 64 + c];
        v.w = bt[(r1 - c + 62) * 8 + h] + mrow[r1 * 64 + c + 1];
        op[wm * 256] = v;
    }
}

// ---------------------------------------------------------------------------
// Kernel k1/k3: 3-stage cp.async mma.sync tf32 GEMM (R9/R10 proven version).
// ---------------------------------------------------------------------------
#define BM 128
#define BK 32
#define KP 36
#define STG (BM * KP)
#define NST 3
#define GEMM_SMEM (2 * NST * STG * 4)       // 110592 B

__global__ void __launch_bounds__(256, 2) gemm_tf32(
    const float* __restrict__ A, const float* __restrict__ BT,
    const float* __restrict__ bias, float* __restrict__ C, int ncols)
{
    extern __shared__ float sm[];
    float* sA = sm;
    float* sB = sm + NST * STG;

    const int t = threadIdx.x;
    const int wid = t >> 5, lane = t & 31;
    const int wm = wid & 3, wn = wid >> 2;
    const int gid = lane >> 2, tig = lane & 3;
    const int n0 = blockIdx.x * BM;
    const int m0 = blockIdx.y * BM;
    const uint32_t sAu = smem_u32(sA);
    const uint32_t sBu = smem_u32(sB);

    auto loadAB = [&](int kc, int s) {
        #pragma unroll
        for (int i = 0; i < 4; i++) {
            int f = t + i * 256;
            int r = f >> 3, c4 = f & 7;
            cp_async16(sAu + (uint32_t)(s * STG + r * KP + c4 * 4) * 4,
                       A + (size_t)(m0 + r) * CDIM + kc * BK + c4 * 4);
        }
        #pragma unroll
        for (int i = 0; i < 4; i++) {
            int f = t + i * 256;
            int r = f >> 3, c4 = f & 7;
            cp_async16(sBu + (uint32_t)(s * STG + r * KP + c4 * 4) * 4,
                       BT + (size_t)(n0 + r) * CDIM + kc * BK + c4 * 4);
        }
    };

    float acc[2][8][4];
    #pragma unroll
    for (int mt = 0; mt < 2; mt++)
        #pragma unroll
        for (int nt = 0; nt < 8; nt++)
            #pragma unroll
            for (int e = 0; e < 4; e++) acc[mt][nt][e] = 0.0f;

    loadAB(0, 0); cp_commit();
    loadAB(1, 1); cp_commit();

    #pragma unroll 1
    for (int kc = 0; kc < CDIM / BK; kc++) {
        if (kc < CDIM / BK - 1) cp_wait<1>(); else cp_wait<0>();
        __syncthreads();

        const float* a_s = sA + (kc % NST) * STG;
        const float* b_s = sB + (kc % NST) * STG;
        #pragma unroll
        for (int kk = 0; kk < BK; kk += 8) {
            uint32_t af[2][4], bf[8][2];
            #pragma unroll
            for (int mt = 0; mt < 2; mt++) {
                const float* ap = a_s + (wm * 32 + mt * 16 + gid) * KP + kk + tig;
                af[mt][0] = __float_as_uint(ap[0]);
                af[mt][1] = __float_as_uint(ap[8 * KP]);
                af[mt][2] = __float_as_uint(ap[4]);
                af[mt][3] = __float_as_uint(ap[8 * KP + 4]);
            }
            #pragma unroll
            for (int nt = 0; nt < 8; nt++) {
                const float* bp = b_s + (wn * 64 + nt * 8 + gid) * KP + kk + tig;
                bf[nt][0] = __float_as_uint(bp[0]);
                bf[nt][1] = __float_as_uint(bp[4]);
            }
            #pragma unroll
            for (int mt = 0; mt < 2; mt++)
                #pragma unroll
                for (int nt = 0; nt < 8; nt++)
                    mma_tf32(acc[mt][nt], af[mt], bf[nt]);
        }
        if (kc + 2 < CDIM / BK) { loadAB(kc + 2, (kc + 2) % NST); cp_commit(); }
    }

    #pragma unroll
    for (int mt = 0; mt < 2; mt++) {
        const int r = m0 + wm * 32 + mt * 16 + gid;
        #pragma unroll
        for (int nt = 0; nt < 8; nt++) {
            const int c = n0 + wn * 64 + nt * 8 + tig * 2;
            float b0 = __ldg(bias + c), b1 = __ldg(bias + c + 1);
            float2 v0 = make_float2(acc[mt][nt][0] + b0, acc[mt][nt][1] + b1);
            float2 v1 = make_float2(acc[mt][nt][2] + b0, acc[mt][nt][3] + b1);
            *(float2*)(C + (size_t)r * ncols + c)       = v0;
            *(float2*)(C + (size_t)(r + 8) * ncols + c) = v1;
        }
    }
}

// ---------------------------------------------------------------------------
// Kernel k2: tensor-core attention (R10 structure), 3 CTAs/SM.
// 2 warp-groups; wg handles head (hp*2+wg), hp=0..3; per-wg named barriers.
// NEW: sP aliases sQ+sK (dead after S=QK^T, guarded by a wg bar.sync) ->
// smem 90112 -> 55296 B -> 3 CTAs/SM.
// ---------------------------------------------------------------------------
#define QP 36
#define PP 68
#define WGF 6912                            // floats per wg region
#define OFF_WG(wg)  ((wg) * WGF)
#define WATTN_SMEM  (2 * WGF * 4)           // 55296 B -> 3 CTAs/SM

__global__ void __launch_bounds__(256, 3) wattn(
    const float* __restrict__ qkv, const float4* __restrict__ bmt,
    float* __restrict__ O)
{
    extern __shared__ float sm[];
    const int t = threadIdx.x, wid = t >> 5, lane = t & 31;
    const int wg = wid >> 2, wm = wid & 3;
    const int gid = lane >> 2, tig = lane & 3;
    const int tt = t & 127;
    const int b = blockIdx.x;
    const int barid = 1 + wg;

    float* sQ = sm + OFF_WG(wg);            // [64][36]
    float* sK = sQ + 2304;                  // [64][36]
    float* sV = sQ + 4608;                  // [64][36]
    float* sP = sQ;                         // [64][68] aliases Q+K (4352 <= 4608)

    const float* base = qkv + (size_t)b * (64 * 768);
    float* og = O + (size_t)b * (64 * 256);

    // Prefetch head hp=0 Q/K into registers.
    float4 pq[4], pk[4];
    #pragma unroll
    for (int i = 0; i < 4; i++) {
        int u = tt + i * 128;
        int n = u >> 3, q = u & 7;
        const float4* rp = (const float4*)(base + n * 768 + wg * 32) + q;
        pq[i] = rp[0];
        pk[i] = rp[64];
    }

    const int r0 = wm * 16 + gid, r1 = r0 + 8;

    for (int hp = 0; hp < 4; hp++) {
        const int h = hp * 2 + wg;
        asm volatile("bar.sync %0, 128;" :: "r"(barid) : "memory");  // prev head reads done

        // Stage Q,K from prefetched regs; V direct (all float4 STS).
        #pragma unroll
        for (int i = 0; i < 4; i++) {
            int u = tt + i * 128;
            int n = u >> 3, q = u & 7;
            float4 qa = pq[i];
            qa.x = tf32r(qa.x); qa.y = tf32r(qa.y); qa.z = tf32r(qa.z); qa.w = tf32r(qa.w);
            *(float4*)&sQ[n * QP + q * 4] = qa;
            float4 ka = pk[i];
            ka.x = tf32r(ka.x); ka.y = tf32r(ka.y); ka.z = tf32r(ka.z); ka.w = tf32r(ka.w);
            *(float4*)&sK[n * QP + q * 4] = ka;
            float4 va = *((const float4*)(base + n * 768 + h * 32) + q + 128);
            va.x = tf32r(va.x); va.y = tf32r(va.y); va.z = tf32r(va.z); va.w = tf32r(va.w);
            *(float4*)&sV[n * QP + q * 4] = va;
        }
        asm volatile("bar.sync %0, 128;" :: "r"(barid) : "memory");  // staging visible

        // Prefetch bias+mask fragments (coalesced LDG.128 from L2).
        float4 bm[8];
        {
            const float4* bmp = bmt + (size_t)((h << 6) | (b & 63)) * 1024
                              + wm * 256 + gid * 4 + tig;
            #pragma unroll
            for (int nt = 0; nt < 8; nt++) bm[nt] = __ldg(bmp + nt * 32);
        }

        // Prefetch next head's Q/K (overlaps with compute below).
        if (hp < 3) {
            #pragma unroll
            for (int i = 0; i < 4; i++) {
                int u = tt + i * 128;
                int n = u >> 3, q = u & 7;
                const float4* rp = (const float4*)(base + n * 768 + (h + 2) * 32) + q;
                pq[i] = rp[0];
                pk[i] = rp[64];
            }
        }

        // S = Q K^T : warp rows wm*16..+15, 64 cols (8 n-tiles).
        float sacc[8][4];
        #pragma unroll
        for (int nt = 0; nt < 8; nt++)
            #pragma unroll
            for (int e = 0; e < 4; e++) sacc[nt][e] = 0.0f;
        #pragma unroll
        for (int kt = 0; kt < 4; kt++) {
            uint32_t af[4];
            const float* ap = sQ + r0 * QP + kt * 8 + tig;
            af[0] = __float_as_uint(ap[0]);
            af[1] = __float_as_uint(ap[8 * QP]);
            af[2] = __float_as_uint(ap[4]);
            af[3] = __float_as_uint(ap[8 * QP + 4]);
            #pragma unroll
            for (int nt = 0; nt < 8; nt++) {
                uint32_t bf[2];
                const float* bp = sK + (nt * 8 + gid) * QP + kt * 8 + tig;
                bf[0] = __float_as_uint(bp[0]);
                bf[1] = __float_as_uint(bp[4]);
                mma_tf32(sacc[nt], af, bf);
            }
        }

        // Softmax rows r0,r1; bias+mask from registers.
        float v0[16], v1[16];
        #pragma unroll
        for (int nt = 0; nt < 8; nt++) {
            v0[nt * 2 + 0] = fmaf(sacc[nt][0], SCALEF, bm[nt].x);
            v0[nt * 2 + 1] = fmaf(sacc[nt][1], SCALEF, bm[nt].y);
            v1[nt * 2 + 0] = fmaf(sacc[nt][2], SCALEF, bm[nt].z);
            v1[nt * 2 + 1] = fmaf(sacc[nt][3], SCALEF, bm[nt].w);
        }
        float mx0 = -1e30f, mx1 = -1e30f;
        #pragma unroll
        for (int i = 0; i < 16; i++) { mx0 = fmaxf(mx0, v0[i]); mx1 = fmaxf(mx1, v1[i]); }
        mx0 = fmaxf(mx0, __shfl_xor_sync(0xffffffffu, mx0, 1));
        mx0 = fmaxf(mx0, __shfl_xor_sync(0xffffffffu, mx0, 2));
        mx1 = fmaxf(mx1, __shfl_xor_sync(0xffffffffu, mx1, 1));
        mx1 = fmaxf(mx1, __shfl_xor_sync(0xffffffffu, mx1, 2));
        float s0 = 0.0f, s1 = 0.0f;
        #pragma unroll
        for (int i = 0; i < 16; i++) {
            v0[i] = __expf(v0[i] - mx0); s0 += v0[i];
            v1[i] = __expf(v1[i] - mx1); s1 += v1[i];
        }
        s0 += __shfl_xor_sync(0xffffffffu, s0, 1);
        s0 += __shfl_xor_sync(0xffffffffu, s0, 2);
        s1 += __shfl_xor_sync(0xffffffffu, s1, 1);
        s1 += __shfl_xor_sync(0xffffffffu, s1, 2);
        const float i0 = 1.0f / s0, i1 = 1.0f / s1;

        // All wg warps must be done READING sQ/sK before sP (alias) is written.
        asm volatile("bar.sync %0, 128;" :: "r"(barid) : "memory");

        #pragma unroll
        for (int nt = 0; nt < 8; nt++) {
            int c = nt * 8 + tig * 2;
            float2 p0 = make_float2(tf32r(v0[nt * 2] * i0), tf32r(v0[nt * 2 + 1] * i0));
            float2 p1 = make_float2(tf32r(v1[nt * 2] * i1), tf32r(v1[nt * 2 + 1] * i1));
            *(float2*)&sP[r0 * PP + c] = p0;
            *(float2*)&sP[r1 * PP + c] = p1;
        }
        __syncwarp();   // P rows read back are warp-private

        // O = P @ V : 4 n-tiles over head dim 32, k=64.  B-frag from natural V.
        float oacc[4][4];
        #pragma unroll
        for (int nt = 0; nt < 4; nt++)
            #pragma unroll
            for (int e = 0; e < 4; e++) oacc[nt][e] = 0.0f;
        #pragma unroll
        for (int kt = 0; kt < 8; kt++) {
            uint32_t af[4];
            const float* pp = sP + r0 * PP + kt * 8 + tig;
            af[0] = __float_as_uint(pp[0]);
            af[1] = __float_as_uint(pp[8 * PP]);
            af[2] = __float_as_uint(pp[4]);
            af[3] = __float_as_uint(pp[8 * PP + 4]);
            #pragma unroll
            for (int nt = 0; nt < 4; nt++) {
                uint32_t bf[2];
                const float* vp = sV + (kt * 8 + tig) * QP + nt * 8 + gid;
                bf[0] = __float_as_uint(vp[0]);
                bf[1] = __float_as_uint(vp[4 * QP]);
                mma_tf32(oacc[nt], af, bf);
            }
        }
        #pragma unroll
        for (int nt = 0; nt < 4; nt++) {
            const int c = h * 32 + nt * 8 + tig * 2;
            *(float2*)&og[r0 * 256 + c] =
                make_float2(tf32r(oacc[nt][0]), tf32r(oacc[nt][1]));
            *(float2*)&og[r1 * 256 + c] =
                make_float2(tf32r(oacc[nt][2]), tf32r(oacc[nt][3]));
        }
    }
}

// ---------------------------------------------------------------------------
extern "C" void kernel_launch(void* const* d_in, const int* in_sizes, int n_in,
                              void* d_out, int out_size)
{
    const float* x          = (const float*)d_in[0];
    const float* mask       = (const float*)d_in[1];
    const float* wqkv       = (const float*)d_in[2];
    const float* bqkv       = (const float*)d_in[3];
    const float* wproj      = (const float*)d_in[4];
    const float* bproj      = (const float*)d_in[5];
    const float* bias_table = (const float*)d_in[6];
    (void)in_sizes; (void)n_in; (void)out_size;

    cudaFuncSetAttribute(gemm_tf32, cudaFuncAttributeMaxDynamicSharedMemorySize, GEMM_SMEM);
    cudaFuncSetAttribute(wattn, cudaFuncAttributeMaxDynamicSharedMemorySize, WATTN_SMEM);

    float *qkvT, *projT, *qkvS, *oS, *xr;
    float4* bmT;
    cudaGetSymbolAddress((void**)&qkvT,  g_WqkvT);
    cudaGetSymbolAddress((void**)&projT, g_WprojT);
    cudaGetSymbolAddress((void**)&qkvS,  g_QKV);
    cudaGetSymbolAddress((void**)&oS,    g_O);
    cudaGetSymbolAddress((void**)&xr,    g_Xr);
    cudaGetSymbolAddress((void**)&bmT,   g_BM);

    round_tf32<<<65536, 256>>>((const float4*)x, (float4*)xr);
    transpose_tf32<<<dim3(24, 8), dim3(32, 8)>>>(wqkv,  qkvT, 768);
    transpose_tf32<<<dim3(8, 8),  dim3(32, 8)>>>(wproj, projT, 256);
    bm_build<<<512, 256>>>(mask, bias_table, bmT);
    gemm_tf32<<<dim3(6, 2048), 256, GEMM_SMEM>>>(xr, qkvT, bqkv, qkvS, 768);
    wattn<<<NWIN, 256, WATTN_SMEM>>>(qkvS, bmT, oS);
    gemm_tf32<<<dim3(2, 2048), 256, GEMM_SMEM>>>(oS, projT, bproj, (float*)d_out, 256);
}

// round 13
// speedup vs baseline: 1.4969x; 1.4969x over previous
#include <cuda_runtime.h>
#include <cstdint>

// Window attention: B_=4096 windows, N=64 tok, C=256, H=8 heads, D=32. fp32 I/O.
//   r0: g_Xr = tf32-round(x)
//   t0: transpose+round w_qkv/w_proj -> g_W*T (tf32)
//   b0: g_BM[h][w] = bias+mask in MMA-fragment order
//   k1: 3-stage cp.async mma.sync tf32 GEMM, grid (n,m) for L2 reuse of A
//   k2: mma.sync tf32 attention; 128-thr CTAs (1 warpgroup), 5 CTAs/SM
//   k3: same GEMM for proj
// (PTX target compute_103: tcgen05 unavailable; legacy mma.sync tf32 path.)

#define NWIN   4096
#define CDIM   256
#define NHEAD  8
#define SCALEF 0.17677669529663687f

__device__ float  g_QKV[(size_t)NWIN * 64 * 768];
__device__ float  g_O  [(size_t)NWIN * 64 * 256];
__device__ float  g_Xr [(size_t)NWIN * 64 * 256];
__device__ float  g_WqkvT [768 * 256];
__device__ float  g_WprojT[256 * 256];
__device__ float4 g_BM[8 * 64 * 1024];      // 8 MB: [h][w][wm][nt][gid][tig]

__device__ __forceinline__ float tf32r(float x) {
    float y; asm("cvt.rna.tf32.f32 %0, %1;" : "=f"(y) : "f"(x)); return y;
}
__device__ __forceinline__ uint32_t smem_u32(const void* p) {
    uint32_t a;
    asm("{ .reg .u64 t; cvta.to.shared.u64 t, %1; cvt.u32.u64 %0, t; }" : "=r"(a) : "l"(p));
    return a;
}
__device__ __forceinline__ void cp_async16(uint32_t dst, const void* src) {
    asm volatile("cp.async.cg.shared.global [%0], [%1], 16;" :: "r"(dst), "l"(src));
}
__device__ __forceinline__ void cp_commit() {
    asm volatile("cp.async.commit_group;" ::: "memory");
}
template<int N> __device__ __forceinline__ void cp_wait() {
    asm volatile("cp.async.wait_group %0;" :: "n"(N) : "memory");
}

// m16n8k8 tf32 mma: D += A(16x8,row) * B(8x8,col).
__device__ __forceinline__ void mma_tf32(float* d, const uint32_t* a, const uint32_t* b) {
    asm volatile(
        "mma.sync.aligned.m16n8k8.row.col.f32.tf32.tf32.f32 "
        "{%0,%1,%2,%3}, {%4,%5,%6,%7}, {%8,%9}, {%0,%1,%2,%3};"
        : "+f"(d[0]), "+f"(d[1]), "+f"(d[2]), "+f"(d[3])
        : "r"(a[0]), "r"(a[1]), "r"(a[2]), "r"(a[3]), "r"(b[0]), "r"(b[1]));
}

// ---------------------------------------------------------------------------
// Kernel r0: elementwise tf32 rounding (float4).
// ---------------------------------------------------------------------------
__global__ void round_tf32(const float4* __restrict__ in, float4* __restrict__ out)
{
    int i = blockIdx.x * blockDim.x + threadIdx.x;
    float4 v = in[i];
    v.x = tf32r(v.x); v.y = tf32r(v.y); v.z = tf32r(v.z); v.w = tf32r(v.w);
    out[i] = v;
}

// ---------------------------------------------------------------------------
// Kernel t0: transpose src[256, ncol] -> dst[ncol, 256], tf32-rounded.
// ---------------------------------------------------------------------------
__global__ void transpose_tf32(const float* __restrict__ src, float* __restrict__ dst, int ncol)
{
    __shared__ float tile[32][33];
    const int bx = blockIdx.x, by = blockIdx.y;
    const int tx = threadIdx.x, ty0 = threadIdx.y;
    #pragma unroll
    for (int j = 0; j < 32; j += 8)
        tile[ty0 + j][tx] = src[(size_t)(by * 32 + ty0 + j) * ncol + bx * 32 + tx];
    __syncthreads();
    #pragma unroll
    for (int j = 0; j < 32; j += 8)
        dst[(size_t)(bx * 32 + ty0 + j) * 256 + by * 32 + tx] = tf32r(tile[tx][ty0 + j]);
}

// ---------------------------------------------------------------------------
// Kernel b0: build bias+mask fragment table.
// ---------------------------------------------------------------------------
__global__ void bm_build(const float* __restrict__ mask, const float* __restrict__ bt,
                         float4* __restrict__ out)
{
    const int hw = blockIdx.x;             // 0..511
    const int h = hw >> 6, w = hw & 63;
    const int t = threadIdx.x;             // 256
    const int nt = t >> 5, gid = (t >> 2) & 7, tig = t & 3;
    const float* mrow = mask + (size_t)w * 4096;
    float4* op = out + (size_t)hw * 1024 + nt * 32 + gid * 4 + tig;
    const int c = nt * 8 + tig * 2;
    #pragma unroll
    for (int wm = 0; wm < 4; wm++) {
        const int r0 = wm * 16 + gid, r1 = r0 + 8;
        float4 v;
        v.x = bt[(r0 - c + 63) * 8 + h] + mrow[r0 * 64 + c];
        v.y = bt[(r0 - c + 62) * 8 + h] + mrow[r0 * 64 + c + 1];
        v.z = bt[(r1 - c + 63) * 8 + h] + mrow[r1 * 64 + c];
        v.w = bt[(r1 - c + 62) * 8 + h] + mrow[r1 * 64 + c + 1];
        op[wm * 256] = v;
    }
}

// ---------------------------------------------------------------------------
// Kernel k1/k3: 3-stage cp.async mma.sync tf32 GEMM (R9/R10 proven version).
// ---------------------------------------------------------------------------
#define BM 128
#define BK 32
#define KP 36
#define STG (BM * KP)
#define NST 3
#define GEMM_SMEM (2 * NST * STG * 4)       // 110592 B

__global__ void __launch_bounds__(256, 2) gemm_tf32(
    const float* __restrict__ A, const float* __restrict__ BT,
    const float* __restrict__ bias, float* __restrict__ C, int ncols)
{
    extern __shared__ float sm[];
    float* sA = sm;
    float* sB = sm + NST * STG;

    const int t = threadIdx.x;
    const int wid = t >> 5, lane = t & 31;
    const int wm = wid & 3, wn = wid >> 2;
    const int gid = lane >> 2, tig = lane & 3;
    const int n0 = blockIdx.x * BM;
    const int m0 = blockIdx.y * BM;
    const uint32_t sAu = smem_u32(sA);
    const uint32_t sBu = smem_u32(sB);

    auto loadAB = [&](int kc, int s) {
        #pragma unroll
        for (int i = 0; i < 4; i++) {
            int f = t + i * 256;
            int r = f >> 3, c4 = f & 7;
            cp_async16(sAu + (uint32_t)(s * STG + r * KP + c4 * 4) * 4,
                       A + (size_t)(m0 + r) * CDIM + kc * BK + c4 * 4);
        }
        #pragma unroll
        for (int i = 0; i < 4; i++) {
            int f = t + i * 256;
            int r = f >> 3, c4 = f & 7;
            cp_async16(sBu + (uint32_t)(s * STG + r * KP + c4 * 4) * 4,
                       BT + (size_t)(n0 + r) * CDIM + kc * BK + c4 * 4);
        }
    };

    float acc[2][8][4];
    #pragma unroll
    for (int mt = 0; mt < 2; mt++)
        #pragma unroll
        for (int nt = 0; nt < 8; nt++)
            #pragma unroll
            for (int e = 0; e < 4; e++) acc[mt][nt][e] = 0.0f;

    loadAB(0, 0); cp_commit();
    loadAB(1, 1); cp_commit();

    #pragma unroll 1
    for (int kc = 0; kc < CDIM / BK; kc++) {
        if (kc < CDIM / BK - 1) cp_wait<1>(); else cp_wait<0>();
        __syncthreads();

        const float* a_s = sA + (kc % NST) * STG;
        const float* b_s = sB + (kc % NST) * STG;
        #pragma unroll
        for (int kk = 0; kk < BK; kk += 8) {
            uint32_t af[2][4], bf[8][2];
            #pragma unroll
            for (int mt = 0; mt < 2; mt++) {
                const float* ap = a_s + (wm * 32 + mt * 16 + gid) * KP + kk + tig;
                af[mt][0] = __float_as_uint(ap[0]);
                af[mt][1] = __float_as_uint(ap[8 * KP]);
                af[mt][2] = __float_as_uint(ap[4]);
                af[mt][3] = __float_as_uint(ap[8 * KP + 4]);
            }
            #pragma unroll
            for (int nt = 0; nt < 8; nt++) {
                const float* bp = b_s + (wn * 64 + nt * 8 + gid) * KP + kk + tig;
                bf[nt][0] = __float_as_uint(bp[0]);
                bf[nt][1] = __float_as_uint(bp[4]);
            }
            #pragma unroll
            for (int mt = 0; mt < 2; mt++)
                #pragma unroll
                for (int nt = 0; nt < 8; nt++)
                    mma_tf32(acc[mt][nt], af[mt], bf[nt]);
        }
        if (kc + 2 < CDIM / BK) { loadAB(kc + 2, (kc + 2) % NST); cp_commit(); }
    }

    #pragma unroll
    for (int mt = 0; mt < 2; mt++) {
        const int r = m0 + wm * 32 + mt * 16 + gid;
        #pragma unroll
        for (int nt = 0; nt < 8; nt++) {
            const int c = n0 + wn * 64 + nt * 8 + tig * 2;
            float b0 = __ldg(bias + c), b1 = __ldg(bias + c + 1);
            float2 v0 = make_float2(acc[mt][nt][0] + b0, acc[mt][nt][1] + b1);
            float2 v1 = make_float2(acc[mt][nt][2] + b0, acc[mt][nt][3] + b1);
            *(float2*)(C + (size_t)r * ncols + c)       = v0;
            *(float2*)(C + (size_t)(r + 8) * ncols + c) = v1;
        }
    }
}

// ---------------------------------------------------------------------------
// Kernel k2: tensor-core attention (R10 structure), 128-thread CTAs.
// Grid (4096, 2): blockIdx.x = window, blockIdx.y = former warp-group.
// One warpgroup per CTA -> __syncthreads replaces named barriers; smem
// 45056 B/CTA -> 5 CTAs/SM (20 warps), reg cap 102 (no spill).
// ---------------------------------------------------------------------------
#define QP 36
#define PP 68
#define WATTN_SMEM (11264 * 4)              // 45056 B

__global__ void __launch_bounds__(128, 5) wattn(
    const float* __restrict__ qkv, const float4* __restrict__ bmt,
    float* __restrict__ O)
{
    extern __shared__ float sm[];
    const int t = threadIdx.x, wid = t >> 5, lane = t & 31;
    const int wm = wid;                      // 4 warps: m-rows
    const int gid = lane >> 2, tig = lane & 3;
    const int b = blockIdx.x;
    const int wg = blockIdx.y;               // head parity

    float* sQ = sm;                          // [64][36]
    float* sK = sm + 2304;                   // [64][36]
    float* sV = sm + 4608;                   // [64][36]
    float* sP = sm + 6912;                   // [64][68]

    const float* base = qkv + (size_t)b * (64 * 768);
    float* og = O + (size_t)b * (64 * 256);

    // Prefetch head hp=0 Q/K into registers.
    float4 pq[4], pk[4];
    #pragma unroll
    for (int i = 0; i < 4; i++) {
        int u = t + i * 128;
        int n = u >> 3, q = u & 7;
        const float4* rp = (const float4*)(base + n * 768 + wg * 32) + q;
        pq[i] = rp[0];
        pk[i] = rp[64];
    }

    const int r0 = wm * 16 + gid, r1 = r0 + 8;

    for (int hp = 0; hp < 4; hp++) {
        const int h = hp * 2 + wg;
        __syncthreads();                     // prev head smem reads done

        // Stage Q,K from prefetched regs; V direct (all float4 STS).
        #pragma unroll
        for (int i = 0; i < 4; i++) {
            int u = t + i * 128;
            int n = u >> 3, q = u & 7;
            float4 qa = pq[i];
            qa.x = tf32r(qa.x); qa.y = tf32r(qa.y); qa.z = tf32r(qa.z); qa.w = tf32r(qa.w);
            *(float4*)&sQ[n * QP + q * 4] = qa;
            float4 ka = pk[i];
            ka.x = tf32r(ka.x); ka.y = tf32r(ka.y); ka.z = tf32r(ka.z); ka.w = tf32r(ka.w);
            *(float4*)&sK[n * QP + q * 4] = ka;
            float4 va = *((const float4*)(base + n * 768 + h * 32) + q + 128);
            va.x = tf32r(va.x); va.y = tf32r(va.y); va.z = tf32r(va.z); va.w = tf32r(va.w);
            *(float4*)&sV[n * QP + q * 4] = va;
        }
        __syncthreads();                     // staging visible

        // Prefetch bias+mask fragments (coalesced LDG.128 from L2).
        float4 bm[8];
        {
            const float4* bmp = bmt + (size_t)((h << 6) | (b & 63)) * 1024
                              + wm * 256 + gid * 4 + tig;
            #pragma unroll
            for (int nt = 0; nt < 8; nt++) bm[nt] = __ldg(bmp + nt * 32);
        }

        // Prefetch next head's Q/K (overlaps with compute below).
        if (hp < 3) {
            #pragma unroll
            for (int i = 0; i < 4; i++) {
                int u = t + i * 128;
                int n = u >> 3, q = u & 7;
                const float4* rp = (const float4*)(base + n * 768 + (h + 2) * 32) + q;
                pq[i] = rp[0];
                pk[i] = rp[64];
            }
        }

        // S = Q K^T : warp rows wm*16..+15, 64 cols (8 n-tiles).
        float sacc[8][4];
        #pragma unroll
        for (int nt = 0; nt < 8; nt++)
            #pragma unroll
            for (int e = 0; e < 4; e++) sacc[nt][e] = 0.0f;
        #pragma unroll
        for (int kt = 0; kt < 4; kt++) {
            uint32_t af[4];
            const float* ap = sQ + r0 * QP + kt * 8 + tig;
            af[0] = __float_as_uint(ap[0]);
            af[1] = __float_as_uint(ap[8 * QP]);
            af[2] = __float_as_uint(ap[4]);
            af[3] = __float_as_uint(ap[8 * QP + 4]);
            #pragma unroll
            for (int nt = 0; nt < 8; nt++) {
                uint32_t bf[2];
                const float* bp = sK + (nt * 8 + gid) * QP + kt * 8 + tig;
                bf[0] = __float_as_uint(bp[0]);
                bf[1] = __float_as_uint(bp[4]);
                mma_tf32(sacc[nt], af, bf);
            }
        }

        // Softmax rows r0,r1; bias+mask from registers.
        float v0[16], v1[16];
        #pragma unroll
        for (int nt = 0; nt < 8; nt++) {
            v0[nt * 2 + 0] = fmaf(sacc[nt][0], SCALEF, bm[nt].x);
            v0[nt * 2 + 1] = fmaf(sacc[nt][1], SCALEF, bm[nt].y);
            v1[nt * 2 + 0] = fmaf(sacc[nt][2], SCALEF, bm[nt].z);
            v1[nt * 2 + 1] = fmaf(sacc[nt][3], SCALEF, bm[nt].w);
        }
        float mx0 = -1e30f, mx1 = -1e30f;
        #pragma unroll
        for (int i = 0; i < 16; i++) { mx0 = fmaxf(mx0, v0[i]); mx1 = fmaxf(mx1, v1[i]); }
        mx0 = fmaxf(mx0, __shfl_xor_sync(0xffffffffu, mx0, 1));
        mx0 = fmaxf(mx0, __shfl_xor_sync(0xffffffffu, mx0, 2));
        mx1 = fmaxf(mx1, __shfl_xor_sync(0xffffffffu, mx1, 1));
        mx1 = fmaxf(mx1, __shfl_xor_sync(0xffffffffu, mx1, 2));
        float s0 = 0.0f, s1 = 0.0f;
        #pragma unroll
        for (int i = 0; i < 16; i++) {
            v0[i] = __expf(v0[i] - mx0); s0 += v0[i];
            v1[i] = __expf(v1[i] - mx1); s1 += v1[i];
        }
        s0 += __shfl_xor_sync(0xffffffffu, s0, 1);
        s0 += __shfl_xor_sync(0xffffffffu, s0, 2);
        s1 += __shfl_xor_sync(0xffffffffu, s1, 1);
        s1 += __shfl_xor_sync(0xffffffffu, s1, 2);
        const float i0 = 1.0f / s0, i1 = 1.0f / s1;
        #pragma unroll
        for (int nt = 0; nt < 8; nt++) {
            int c = nt * 8 + tig * 2;
            float2 p0 = make_float2(tf32r(v0[nt * 2] * i0), tf32r(v0[nt * 2 + 1] * i0));
            float2 p1 = make_float2(tf32r(v1[nt * 2] * i1), tf32r(v1[nt * 2 + 1] * i1));
            *(float2*)&sP[r0 * PP + c] = p0;
            *(float2*)&sP[r1 * PP + c] = p1;
        }
        __syncwarp();   // P rows read back are warp-private

        // O = P @ V : 4 n-tiles over head dim 32, k=64.  B-frag from natural V.
        float oacc[4][4];
        #pragma unroll
        for (int nt = 0; nt < 4; nt++)
            #pragma unroll
            for (int e = 0; e < 4; e++) oacc[nt][e] = 0.0f;
        #pragma unroll
        for (int kt = 0; kt < 8; kt++) {
            uint32_t af[4];
            const float* pp = sP + r0 * PP + kt * 8 + tig;
            af[0] = __float_as_uint(pp[0]);
            af[1] = __float_as_uint(pp[8 * PP]);
            af[2] = __float_as_uint(pp[4]);
            af[3] = __float_as_uint(pp[8 * PP + 4]);
            #pragma unroll
            for (int nt = 0; nt < 4; nt++) {
                uint32_t bf[2];
                const float* vp = sV + (kt * 8 + tig) * QP + nt * 8 + gid;
                bf[0] = __float_as_uint(vp[0]);
                bf[1] = __float_as_uint(vp[4 * QP]);
                mma_tf32(oacc[nt], af, bf);
            }
        }
        #pragma unroll
        for (int nt = 0; nt < 4; nt++) {
            const int c = h * 32 + nt * 8 + tig * 2;
            *(float2*)&og[r0 * 256 + c] =
                make_float2(tf32r(oacc[nt][0]), tf32r(oacc[nt][1]));
            *(float2*)&og[r1 * 256 + c] =
                make_float2(tf32r(oacc[nt][2]), tf32r(oacc[nt][3]));
        }
    }
}

// ---------------------------------------------------------------------------
extern "C" void kernel_launch(void* const* d_in, const int* in_sizes, int n_in,
                              void* d_out, int out_size)
{
    const float* x          = (const float*)d_in[0];
    const float* mask       = (const float*)d_in[1];
    const float* wqkv       = (const float*)d_in[2];
    const float* bqkv       = (const float*)d_in[3];
    const float* wproj      = (const float*)d_in[4];
    const float* bproj      = (const float*)d_in[5];
    const float* bias_table = (const float*)d_in[6];
    (void)in_sizes; (void)n_in; (void)out_size;

    cudaFuncSetAttribute(gemm_tf32, cudaFuncAttributeMaxDynamicSharedMemorySize, GEMM_SMEM);
    cudaFuncSetAttribute(wattn, cudaFuncAttributeMaxDynamicSharedMemorySize, WATTN_SMEM);

    float *qkvT, *projT, *qkvS, *oS, *xr;
    float4* bmT;
    cudaGetSymbolAddress((void**)&qkvT,  g_WqkvT);
    cudaGetSymbolAddress((void**)&projT, g_WprojT);
    cudaGetSymbolAddress((void**)&qkvS,  g_QKV);
    cudaGetSymbolAddress((void**)&oS,    g_O);
    cudaGetSymbolAddress((void**)&xr,    g_Xr);
    cudaGetSymbolAddress((void**)&bmT,   g_BM);

    round_tf32<<<65536, 256>>>((const float4*)x, (float4*)xr);
    transpose_tf32<<<dim3(24, 8), dim3(32, 8)>>>(wqkv,  qkvT, 768);
    transpose_tf32<<<dim3(8, 8),  dim3(32, 8)>>>(wproj, projT, 256);
    bm_build<<<512, 256>>>(mask, bias_table, bmT);
    gemm_tf32<<<dim3(6, 2048), 256, GEMM_SMEM>>>(xr, qkvT, bqkv, qkvS, 768);
    wattn<<<dim3(NWIN, 2), 128, WATTN_SMEM>>>(qkvS, bmT, oS);
    gemm_tf32<<<dim3(2, 2048), 256, GEMM_SMEM>>>(oS, projT, bproj, (float*)d_out, 256);
}

// round 14
// speedup vs baseline: 1.5126x; 1.0105x over previous
#include <cuda_runtime.h>
#include <cstdint>

// Window attention: B_=4096 windows, N=64 tok, C=256, H=8 heads, D=32. fp32 I/O.
//   r0: g_Xr = tf32-round(x), k-PERMUTED groups of 8 (phys = logical [0,4,1,5,2,6,3,7])
//   t0: transpose+round weights -> g_W*T, same k-permutation
//   b0: g_BM[h][w] = bias+mask in MMA-fragment order
//   k1: 3-stage cp.async mma.sync tf32 GEMM, XOR-swizzled stride-32 smem,
//       float2 fragment loads (permuted-k), grid (n,m) for L2 reuse
//   k2: mma.sync tf32 attention (R10 version); g_O stores k-permuted
//   k3: same GEMM for proj (output natural)
// (PTX target compute_103: tcgen05 unavailable; legacy mma.sync tf32 path.)

#define NWIN   4096
#define CDIM   256
#define NHEAD  8
#define SCALEF 0.17677669529663687f

__device__ float  g_QKV[(size_t)NWIN * 64 * 768];
__device__ float  g_O  [(size_t)NWIN * 64 * 256];
__device__ float  g_Xr [(size_t)NWIN * 64 * 256];
__device__ float  g_WqkvT [768 * 256];
__device__ float  g_WprojT[256 * 256];
__device__ float4 g_BM[8 * 64 * 1024];      // 8 MB: [h][w][wm][nt][gid][tig]

__device__ __forceinline__ float tf32r(float x) {
    float y; asm("cvt.rna.tf32.f32 %0, %1;" : "=f"(y) : "f"(x)); return y;
}
__device__ __forceinline__ uint32_t smem_u32(const void* p) {
    uint32_t a;
    asm("{ .reg .u64 t; cvta.to.shared.u64 t, %1; cvt.u32.u64 %0, t; }" : "=r"(a) : "l"(p));
    return a;
}
__device__ __forceinline__ void cp_async16(uint32_t dst, const void* src) {
    asm volatile("cp.async.cg.shared.global [%0], [%1], 16;" :: "r"(dst), "l"(src));
}
__device__ __forceinline__ void cp_commit() {
    asm volatile("cp.async.commit_group;" ::: "memory");
}
template<int N> __device__ __forceinline__ void cp_wait() {
    asm volatile("cp.async.wait_group %0;" :: "n"(N) : "memory");
}

// m16n8k8 tf32 mma: D += A(16x8,row) * B(8x8,col).
__device__ __forceinline__ void mma_tf32(float* d, const uint32_t* a, const uint32_t* b) {
    asm volatile(
        "mma.sync.aligned.m16n8k8.row.col.f32.tf32.tf32.f32 "
        "{%0,%1,%2,%3}, {%4,%5,%6,%7}, {%8,%9}, {%0,%1,%2,%3};"
        : "+f"(d[0]), "+f"(d[1]), "+f"(d[2]), "+f"(d[3])
        : "r"(a[0]), "r"(a[1]), "r"(a[2]), "r"(a[3]), "r"(b[0]), "r"(b[1]));
}

// ---------------------------------------------------------------------------
// Kernel r0: tf32 rounding + k-permutation. One thread = one 8-float group.
// phys[0..7] = logical [0,4,1,5,2,6,3,7].
// ---------------------------------------------------------------------------
__global__ void round_tf32p(const float4* __restrict__ in, float4* __restrict__ out)
{
    int i = blockIdx.x * blockDim.x + threadIdx.x;      // group index
    float4 a = in[2 * i], b = in[2 * i + 1];            // logical 0-3, 4-7
    float4 o0 = make_float4(tf32r(a.x), tf32r(b.x), tf32r(a.y), tf32r(b.y));
    float4 o1 = make_float4(tf32r(a.z), tf32r(b.z), tf32r(a.w), tf32r(b.w));
    out[2 * i]     = o0;
    out[2 * i + 1] = o1;
}

// ---------------------------------------------------------------------------
// Kernel t0: transpose src[256, ncol] -> dst[ncol, 256], tf32-rounded,
// dst columns k-permuted (P[l] = l<4 ? 2l : 2l-7).
// ---------------------------------------------------------------------------
__global__ void transpose_tf32p(const float* __restrict__ src, float* __restrict__ dst, int ncol)
{
    __shared__ float tile[32][33];
    const int bx = blockIdx.x, by = blockIdx.y;
    const int tx = threadIdx.x, ty0 = threadIdx.y;
    #pragma unroll
    for (int j = 0; j < 32; j += 8)
        tile[ty0 + j][tx] = src[(size_t)(by * 32 + ty0 + j) * ncol + bx * 32 + tx];
    __syncthreads();
    const int l = tx & 7;
    const int cphys = (by * 32) + (tx & ~7) + ((l < 4) ? 2 * l : 2 * l - 7);
    #pragma unroll
    for (int j = 0; j < 32; j += 8)
        dst[(size_t)(bx * 32 + ty0 + j) * 256 + cphys] = tf32r(tile[tx][ty0 + j]);
}

// ---------------------------------------------------------------------------
// Kernel b0: build bias+mask fragment table.
// ---------------------------------------------------------------------------
__global__ void bm_build(const float* __restrict__ mask, const float* __restrict__ bt,
                         float4* __restrict__ out)
{
    const int hw = blockIdx.x;             // 0..511
    const int h = hw >> 6, w = hw & 63;
    const int t = threadIdx.x;             // 256
    const int nt = t >> 5, gid = (t >> 2) & 7, tig = t & 3;
    const float* mrow = mask + (size_t)w * 4096;
    float4* op = out + (size_t)hw * 1024 + nt * 32 + gid * 4 + tig;
    const int c = nt * 8 + tig * 2;
    #pragma unroll
    for (int wm = 0; wm < 4; wm++) {
        const int r0 = wm * 16 + gid, r1 = r0 + 8;
        float4 v;
        v.x = bt[(r0 - c + 63) * 8 + h] + mrow[r0 * 64 + c];
        v.y = bt[(r0 - c + 62) * 8 + h] + mrow[r0 * 64 + c + 1];
        v.z = bt[(r1 - c + 63) * 8 + h] + mrow[r1 * 64 + c];
        v.w = bt[(r1 - c + 62) * 8 + h] + mrow[r1 * 64 + c + 1];
        op[wm * 256] = v;
    }
}

// ---------------------------------------------------------------------------
// Kernel k1/k3: 3-stage cp.async mma.sync tf32 GEMM.
// A, BT pre-rounded AND k-permuted. Smem: stride 32 floats/row, 8-float
// blocks XOR-swizzled by (row&3) -> conflict-free float2 fragment loads.
// Pipeline identical to R10 (NST=3, cp_wait<1>, one barrier/chunk).
// ---------------------------------------------------------------------------
#define BM 128
#define BK 32
#define STG (BM * 32)                       // 4096 floats
#define NST 3
#define GEMM_SMEM (2 * NST * STG * 4)       // 98304 B -> 2 CTAs/SM

__global__ void __launch_bounds__(256, 2) gemm_tf32(
    const float* __restrict__ A, const float* __restrict__ BT,
    const float* __restrict__ bias, float* __restrict__ C, int ncols)
{
    extern __shared__ float sm[];
    float* sA = sm;
    float* sB = sm + NST * STG;

    const int t = threadIdx.x;
    const int wid = t >> 5, lane = t & 31;
    const int wm = wid & 3, wn = wid >> 2;
    const int gid = lane >> 2, tig = lane & 3;
    const int g3 = gid & 3;
    const int n0 = blockIdx.x * BM;
    const int m0 = blockIdx.y * BM;
    const uint32_t sAu = smem_u32(sA);
    const uint32_t sBu = smem_u32(sB);

    auto loadAB = [&](int kc, int s) {
        #pragma unroll
        for (int i = 0; i < 4; i++) {
            int f = t + i * 256;
            int r = f >> 3, c4 = f & 7;
            uint32_t off = (uint32_t)(s * STG + r * 32
                         + (((c4 >> 1) ^ (r & 3)) << 3) + ((c4 & 1) << 2)) * 4;
            cp_async16(sAu + off, A + (size_t)(m0 + r) * CDIM + kc * BK + c4 * 4);
        }
        #pragma unroll
        for (int i = 0; i < 4; i++) {
            int f = t + i * 256;
            int r = f >> 3, c4 = f & 7;
            uint32_t off = (uint32_t)(s * STG + r * 32
                         + (((c4 >> 1) ^ (r & 3)) << 3) + ((c4 & 1) << 2)) * 4;
            cp_async16(sBu + off, BT + (size_t)(n0 + r) * CDIM + kc * BK + c4 * 4);
        }
    };

    float acc[2][8][4];
    #pragma unroll
    for (int mt = 0; mt < 2; mt++)
        #pragma unroll
        for (int nt = 0; nt < 8; nt++)
            #pragma unroll
            for (int e = 0; e < 4; e++) acc[mt][nt][e] = 0.0f;

    loadAB(0, 0); cp_commit();
    loadAB(1, 1); cp_commit();

    #pragma unroll 1
    for (int kc = 0; kc < CDIM / BK; kc++) {
        if (kc < CDIM / BK - 1) cp_wait<1>(); else cp_wait<0>();
        __syncthreads();

        const float* a_s = sA + (kc % NST) * STG;
        const float* b_s = sB + (kc % NST) * STG;
        #pragma unroll
        for (int kb = 0; kb < 4; kb++) {
            const int swz = ((kb ^ g3) << 3) | (tig << 1);  // same for A & B rows
            uint32_t af[2][4], bf[8][2];
            #pragma unroll
            for (int mt = 0; mt < 2; mt++) {
                const int R = wm * 32 + mt * 16 + gid;
                float2 a0 = *(const float2*)(a_s + R * 32 + swz);
                float2 a1 = *(const float2*)(a_s + (R + 8) * 32 + swz);
                af[mt][0] = __float_as_uint(a0.x);
                af[mt][2] = __float_as_uint(a0.y);
                af[mt][1] = __float_as_uint(a1.x);
                af[mt][3] = __float_as_uint(a1.y);
            }
            #pragma unroll
            for (int nt = 0; nt < 8; nt++) {
                const int Rb = wn * 64 + nt * 8 + gid;
                float2 b0 = *(const float2*)(b_s + Rb * 32 + swz);
                bf[nt][0] = __float_as_uint(b0.x);
                bf[nt][1] = __float_as_uint(b0.y);
            }
            #pragma unroll
            for (int mt = 0; mt < 2; mt++)
                #pragma unroll
                for (int nt = 0; nt < 8; nt++)
                    mma_tf32(acc[mt][nt], af[mt], bf[nt]);
        }
        if (kc + 2 < CDIM / BK) { loadAB(kc + 2, (kc + 2) % NST); cp_commit(); }
    }

    // Epilogue: bias + store (natural column layout).
    #pragma unroll
    for (int mt = 0; mt < 2; mt++) {
        const int r = m0 + wm * 32 + mt * 16 + gid;
        #pragma unroll
        for (int nt = 0; nt < 8; nt++) {
            const int c = n0 + wn * 64 + nt * 8 + tig * 2;
            float b0 = __ldg(bias + c), b1 = __ldg(bias + c + 1);
            float2 v0 = make_float2(acc[mt][nt][0] + b0, acc[mt][nt][1] + b1);
            float2 v1 = make_float2(acc[mt][nt][2] + b0, acc[mt][nt][3] + b1);
            *(float2*)(C + (size_t)r * ncols + c)       = v0;
            *(float2*)(C + (size_t)(r + 8) * ncols + c) = v1;
        }
    }
}

// ---------------------------------------------------------------------------
// Kernel k2: tensor-core attention (R10-proven version).
// Only change vs R10: g_O stores are k-PERMUTED (feeds the permuted proj GEMM).
// ---------------------------------------------------------------------------
#define QP 36
#define PP 68
#define OFF_Q(wg)   ((wg) * 2304)
#define OFF_K(wg)   (4608 + (wg) * 2304)
#define OFF_V(wg)   (9216 + (wg) * 2304)
#define OFF_P(wg)   (13824 + (wg) * 4352)
#define WATTN_SMEM  ((13824 + 2 * 4352) * 4)   // 90112 B -> 2 CTAs/SM

__global__ void __launch_bounds__(256, 2) wattn(
    const float* __restrict__ qkv, const float4* __restrict__ bmt,
    float* __restrict__ O)
{
    extern __shared__ float sm[];
    const int t = threadIdx.x, wid = t >> 5, lane = t & 31;
    const int wg = wid >> 2, wm = wid & 3;
    const int gid = lane >> 2, tig = lane & 3;
    const int tt = t & 127;
    const int b = blockIdx.x;
    const int barid = 1 + wg;

    float* sQ = sm + OFF_Q(wg);
    float* sK = sm + OFF_K(wg);
    float* sV = sm + OFF_V(wg);
    float* sP = sm + OFF_P(wg);

    const float* base = qkv + (size_t)b * (64 * 768);
    float* og = O + (size_t)b * (64 * 256);

    // Prefetch head hp=0 Q/K into registers.
    float4 pq[4], pk[4];
    #pragma unroll
    for (int i = 0; i < 4; i++) {
        int u = tt + i * 128;
        int n = u >> 3, q = u & 7;
        const float4* rp = (const float4*)(base + n * 768 + wg * 32) + q;
        pq[i] = rp[0];
        pk[i] = rp[64];
    }

    const int r0 = wm * 16 + gid, r1 = r0 + 8;
    // Permuted output positions for logical cols (2tig, 2tig+1):
    // p0 = P[2tig] = [0,4,1,5][tig], second value lands at p0+2.
    const int p0 = ((tig & 1) << 2) | (tig >> 1);

    for (int hp = 0; hp < 4; hp++) {
        const int h = hp * 2 + wg;
        asm volatile("bar.sync %0, 128;" :: "r"(barid) : "memory");  // prev head reads done

        // Stage Q,K from prefetched regs; V direct (all float4 STS).
        #pragma unroll
        for (int i = 0; i < 4; i++) {
            int u = tt + i * 128;
            int n = u >> 3, q = u & 7;
            float4 qa = pq[i];
            qa.x = tf32r(qa.x); qa.y = tf32r(qa.y); qa.z = tf32r(qa.z); qa.w = tf32r(qa.w);
            *(float4*)&sQ[n * QP + q * 4] = qa;
            float4 ka = pk[i];
            ka.x = tf32r(ka.x); ka.y = tf32r(ka.y); ka.z = tf32r(ka.z); ka.w = tf32r(ka.w);
            *(float4*)&sK[n * QP + q * 4] = ka;
            float4 va = *((const float4*)(base + n * 768 + h * 32) + q + 128);
            va.x = tf32r(va.x); va.y = tf32r(va.y); va.z = tf32r(va.z); va.w = tf32r(va.w);
            *(float4*)&sV[n * QP + q * 4] = va;
        }
        asm volatile("bar.sync %0, 128;" :: "r"(barid) : "memory");  // staging visible

        // Prefetch bias+mask fragments (coalesced LDG.128 from L2).
        float4 bm[8];
        {
            const float4* bmp = bmt + (size_t)((h << 6) | (b & 63)) * 1024
                              + wm * 256 + gid * 4 + tig;
            #pragma unroll
            for (int nt = 0; nt < 8; nt++) bm[nt] = __ldg(bmp + nt * 32);
        }

        // Prefetch next head's Q/K (overlaps with compute below).
        if (hp < 3) {
            #pragma unroll
            for (int i = 0; i < 4; i++) {
                int u = tt + i * 128;
                int n = u >> 3, q = u & 7;
                const float4* rp = (const float4*)(base + n * 768 + (h + 2) * 32) + q;
                pq[i] = rp[0];
                pk[i] = rp[64];
            }
        }

        // S = Q K^T : warp rows wm*16..+15, 64 cols (8 n-tiles).
        float sacc[8][4];
        #pragma unroll
        for (int nt = 0; nt < 8; nt++)
            #pragma unroll
            for (int e = 0; e < 4; e++) sacc[nt][e] = 0.0f;
        #pragma unroll
        for (int kt = 0; kt < 4; kt++) {
            uint32_t af[4];
            const float* ap = sQ + r0 * QP + kt * 8 + tig;
            af[0] = __float_as_uint(ap[0]);
            af[1] = __float_as_uint(ap[8 * QP]);
            af[2] = __float_as_uint(ap[4]);
            af[3] = __float_as_uint(ap[8 * QP + 4]);
            #pragma unroll
            for (int nt = 0; nt < 8; nt++) {
                uint32_t bf[2];
                const float* bp = sK + (nt * 8 + gid) * QP + kt * 8 + tig;
                bf[0] = __float_as_uint(bp[0]);
                bf[1] = __float_as_uint(bp[4]);
                mma_tf32(sacc[nt], af, bf);
            }
        }

        // Softmax rows r0,r1; bias+mask from registers.
        float v0[16], v1[16];
        #pragma unroll
        for (int nt = 0; nt < 8; nt++) {
            v0[nt * 2 + 0] = fmaf(sacc[nt][0], SCALEF, bm[nt].x);
            v0[nt * 2 + 1] = fmaf(sacc[nt][1], SCALEF, bm[nt].y);
            v1[nt * 2 + 0] = fmaf(sacc[nt][2], SCALEF, bm[nt].z);
            v1[nt * 2 + 1] = fmaf(sacc[nt][3], SCALEF, bm[nt].w);
        }
        float mx0 = -1e30f, mx1 = -1e30f;
        #pragma unroll
        for (int i = 0; i < 16; i++) { mx0 = fmaxf(mx0, v0[i]); mx1 = fmaxf(mx1, v1[i]); }
        mx0 = fmaxf(mx0, __shfl_xor_sync(0xffffffffu, mx0, 1));
        mx0 = fmaxf(mx0, __shfl_xor_sync(0xffffffffu, mx0, 2));
        mx1 = fmaxf(mx1, __shfl_xor_sync(0xffffffffu, mx1, 1));
        mx1 = fmaxf(mx1, __shfl_xor_sync(0xffffffffu, mx1, 2));
        float s0 = 0.0f, s1 = 0.0f;
        #pragma unroll
        for (int i = 0; i < 16; i++) {
            v0[i] = __expf(v0[i] - mx0); s0 += v0[i];
            v1[i] = __expf(v1[i] - mx1); s1 += v1[i];
        }
        s0 += __shfl_xor_sync(0xffffffffu, s0, 1);
        s0 += __shfl_xor_sync(0xffffffffu, s0, 2);
        s1 += __shfl_xor_sync(0xffffffffu, s1, 1);
        s1 += __shfl_xor_sync(0xffffffffu, s1, 2);
        const float i0 = 1.0f / s0, i1 = 1.0f / s1;
        #pragma unroll
        for (int nt = 0; nt < 8; nt++) {
            int c = nt * 8 + tig * 2;
            float2 pr0 = make_float2(tf32r(v0[nt * 2] * i0), tf32r(v0[nt * 2 + 1] * i0));
            float2 pr1 = make_float2(tf32r(v1[nt * 2] * i1), tf32r(v1[nt * 2 + 1] * i1));
            *(float2*)&sP[r0 * PP + c] = pr0;
            *(float2*)&sP[r1 * PP + c] = pr1;
        }
        __syncwarp();   // P rows read back are warp-private

        // O = P @ V : 4 n-tiles over head dim 32, k=64.  B-frag from natural V.
        float oacc[4][4];
        #pragma unroll
        for (int nt = 0; nt < 4; nt++)
            #pragma unroll
            for (int e = 0; e < 4; e++) oacc[nt][e] = 0.0f;
        #pragma unroll
        for (int kt = 0; kt < 8; kt++) {
            uint32_t af[4];
            const float* pp = sP + r0 * PP + kt * 8 + tig;
            af[0] = __float_as_uint(pp[0]);
            af[1] = __float_as_uint(pp[8 * PP]);
            af[2] = __float_as_uint(pp[4]);
            af[3] = __float_as_uint(pp[8 * PP + 4]);
            #pragma unroll
            for (int nt = 0; nt < 4; nt++) {
                uint32_t bf[2];
                const float* vp = sV + (kt * 8 + tig) * QP + nt * 8 + gid;
                bf[0] = __float_as_uint(vp[0]);
                bf[1] = __float_as_uint(vp[4 * QP]);
                mma_tf32(oacc[nt], af, bf);
            }
        }
        // Permuted stores: logical cols (2tig, 2tig+1) -> phys (p0, p0+2).
        #pragma unroll
        for (int nt = 0; nt < 4; nt++) {
            const int cb = h * 32 + nt * 8;
            og[r0 * 256 + cb + p0]     = tf32r(oacc[nt][0]);
            og[r0 * 256 + cb + p0 + 2] = tf32r(oacc[nt][1]);
            og[r1 * 256 + cb + p0]     = tf32r(oacc[nt][2]);
            og[r1 * 256 + cb + p0 + 2] = tf32r(oacc[nt][3]);
        }
    }
}

// ---------------------------------------------------------------------------
extern "C" void kernel_launch(void* const* d_in, const int* in_sizes, int n_in,
                              void* d_out, int out_size)
{
    const float* x          = (const float*)d_in[0];
    const float* mask       = (const float*)d_in[1];
    const float* wqkv       = (const float*)d_in[2];
    const float* bqkv       = (const float*)d_in[3];
    const float* wproj      = (const float*)d_in[4];
    const float* bproj      = (const float*)d_in[5];
    const float* bias_table = (const float*)d_in[6];
    (void)in_sizes; (void)n_in; (void)out_size;

    cudaFuncSetAttribute(gemm_tf32, cudaFuncAttributeMaxDynamicSharedMemorySize, GEMM_SMEM);
    cudaFuncSetAttribute(wattn, cudaFuncAttributeMaxDynamicSharedMemorySize, WATTN_SMEM);

    float *qkvT, *projT, *qkvS, *oS, *xr;
    float4* bmT;
    cudaGetSymbolAddress((void**)&qkvT,  g_WqkvT);
    cudaGetSymbolAddress((void**)&projT, g_WprojT);
    cudaGetSymbolAddress((void**)&qkvS,  g_QKV);
    cudaGetSymbolAddress((void**)&oS,    g_O);
    cudaGetSymbolAddress((void**)&xr,    g_Xr);
    cudaGetSymbolAddress((void**)&bmT,   g_BM);

    // 67108864 floats = 8388608 groups of 8 -> 32768 blocks x 256 threads.
    round_tf32p<<<32768, 256>>>((const float4*)x, (float4*)xr);
    transpose_tf32p<<<dim3(24, 8), dim3(32, 8)>>>(wqkv,  qkvT, 768);
    transpose_tf32p<<<dim3(8, 8),  dim3(32, 8)>>>(wproj, projT, 256);
    bm_build<<<512, 256>>>(mask, bias_table, bmT);
    gemm_tf32<<<dim3(6, 2048), 256, GEMM_SMEM>>>(xr, qkvT, bqkv, qkvS, 768);
    wattn<<<NWIN, 256, WATTN_SMEM>>>(qkvS, bmT, oS);
    gemm_tf32<<<dim3(2, 2048), 256, GEMM_SMEM>>>(oS, projT, bproj, (float*)d_out, 256);
}